// round 4
// baseline (speedup 1.0000x reference)
#include <cuda_runtime.h>

#define FULL 0xffffffffu
typedef unsigned long long u64;

__device__ __forceinline__ u64 fma2(u64 a, u64 b, u64 c) {
    u64 d;
    asm("fma.rn.f32x2 %0, %1, %2, %3;" : "=l"(d) : "l"(a), "l"(b), "l"(c));
    return d;
}
__device__ __forceinline__ u64 pack2(float lo, float hi) {
    u64 d;
    asm("mov.b64 %0, {%1, %2};" : "=l"(d) : "f"(lo), "f"(hi));
    return d;
}
__device__ __forceinline__ float hadd2(u64 a) {
    float lo, hi;
    asm("mov.b64 {%0, %1}, %2;" : "=f"(lo), "=f"(hi) : "l"(a));
    return lo + hi;
}
// sigmoid(v) = 1 / (1 + 2^(-v*log2e))
__device__ __forceinline__ float fast_sig(float v) {
    float e;
    asm("ex2.approx.f32 %0, %1;" : "=f"(e) : "f"(v * -1.4426950408889634f));
    float r;
    asm("rcp.approx.f32 %0, %1;" : "=f"(r) : "f"(1.0f + e));
    return r;
}
// tanh(v) = 2/(1 + 2^(-2v*log2e)) - 1
__device__ __forceinline__ float fast_tanh(float v) {
    float e;
    asm("ex2.approx.f32 %0, %1;" : "=f"(e) : "f"(v * -2.8853900817779268f));
    float r;
    asm("rcp.approx.f32 %0, %1;" : "=f"(r) : "f"(1.0f + e));
    return fmaf(2.0f, r, -1.0f);
}

// One warp per batch element. lane = hidden unit j (H == 32).
// W_hh rows for this lane's 3 gate outputs are kept packed (f32x2 along k)
// in registers; h lives in a double-buffered shared row per warp.
__global__ void __launch_bounds__(64, 7) gru_fused_kernel(
    const float* __restrict__ x,      // [B, T, 1]
    const float* __restrict__ h0,     // [1, B, 32]
    const float* __restrict__ W_ih,   // [96, 1]
    const float* __restrict__ W_hh,   // [96, 32]
    const float* __restrict__ b_ih,   // [96]
    const float* __restrict__ b_hh,   // [96]
    const float* __restrict__ W_out,  // [1, 32]
    const float* __restrict__ b_out,  // [1]
    float* __restrict__ y,            // [B, T, 1]
    float* __restrict__ h_n,          // [1, B, 32]
    int B, int T)
{
    const int warp = threadIdx.x >> 5;
    const int lane = threadIdx.x & 31;
    const int b = blockIdx.x * 2 + warp;
    if (b >= B) return;

    __shared__ __align__(16) float hbuf[2][2][32];  // [parity][warp][j]

    // ---- load packed recurrent weights: 48 x b64 = 96 regs ----
    const u64* W2 = (const u64*)W_hh;  // row j = 16 packed pairs, 128B-aligned
    u64 wr[16], wz[16], wn[16];
#pragma unroll
    for (int p = 0; p < 16; ++p) {
        wr[p] = W2[(0  + lane) * 16 + p];
        wz[p] = W2[(32 + lane) * 16 + p];
        wn[p] = W2[(64 + lane) * 16 + p];
    }
    const float wihr = W_ih[lane], wihz = W_ih[32 + lane], wihn = W_ih[64 + lane];
    const u64 b2r = pack2(b_ih[lane]      + b_hh[lane],      0.0f);
    const u64 b2z = pack2(b_ih[32 + lane] + b_hh[32 + lane], 0.0f);
    const u64 b2n = pack2(b_hh[64 + lane],                   0.0f);
    const float bihn = b_ih[64 + lane];
    const float wout = W_out[lane];
    const float bout = b_out[0];

    const float* xb = x + (long long)b * T;
    float*       yb = y + (long long)b * T;

    float hj = h0[b * 32 + lane];
    hbuf[0][warp][lane] = hj;
    __syncwarp();

    const int nChunks = T >> 5;  // T is a multiple of 32
    float xv = xb[lane];         // prefetch chunk 0 (lane-strided x values)

    for (int c = 0; c < nChunks; ++c) {
        const float xcur = xv;
        if (c + 1 < nChunks) xv = xb[(c + 1) * 32 + lane];  // prefetch next chunk
        float ybuf = 0.0f;

#pragma unroll 4
        for (int s = 0; s < 32; ++s) {
            const int t = (c << 5) + s;
            // Load the 128B h row as 8x LDS.128 (16B-aligned broadcast reads).
            const ulonglong2* h4 = (const ulonglong2*)hbuf[t & 1][warp];
            u64 h[16];
#pragma unroll
            for (int q = 0; q < 8; ++q) {
                const ulonglong2 v2 = h4[q];
                h[2 * q]     = v2.x;
                h[2 * q + 1] = v2.y;
            }

            u64 ar = b2r, az = b2z, an = b2n;
#pragma unroll
            for (int p = 0; p < 16; ++p) {
                ar = fma2(wr[p], h[p], ar);
                az = fma2(wz[p], h[p], az);
                an = fma2(wn[p], h[p], an);
            }

            const float xt = __shfl_sync(FULL, xcur, s);
            const float r = fast_sig(fmaf(xt, wihr, hadd2(ar)));
            const float z = fast_sig(fmaf(xt, wihz, hadd2(az)));
            const float npre = fmaf(r, hadd2(an), fmaf(xt, wihn, bihn));
            const float n = fast_tanh(npre);

            hj = fmaf(z, hj - n, n);              // (1-z)*n + z*h
            hbuf[(t + 1) & 1][warp][lane] = hj;

            // y_t = W_out . h_t + b_out   (butterfly reduce, park in lane t%32)
            float v = hj * wout;
#pragma unroll
            for (int o = 16; o > 0; o >>= 1) v += __shfl_xor_sync(FULL, v, o);
            if (lane == s) ybuf = v + bout;

            __syncwarp();  // orders STS(h_new) before next step's LDS
        }
        yb[(c << 5) + lane] = ybuf;  // coalesced y write, 32 timesteps at once
    }

    h_n[b * 32 + lane] = hj;
}

extern "C" void kernel_launch(void* const* d_in, const int* in_sizes, int n_in,
                              void* d_out, int out_size) {
    const float* x     = (const float*)d_in[0];
    const float* h0    = (const float*)d_in[1];
    const float* W_ih  = (const float*)d_in[2];
    const float* W_hh  = (const float*)d_in[3];
    const float* b_ih  = (const float*)d_in[4];
    const float* b_hh  = (const float*)d_in[5];
    const float* W_out = (const float*)d_in[6];
    const float* b_out = (const float*)d_in[7];

    const int B = in_sizes[1] / 32;      // h_state is [1, B, 32]
    const int T = in_sizes[0] / B;       // x is [B, T, 1]

    float* out = (float*)d_out;
    float* y   = out;                          // [B, T, 1]
    float* h_n = out + (size_t)B * T;          // [1, B, 32]

    const int blocks = (B + 1) / 2;            // 2 warps (2 batches) per CTA
    gru_fused_kernel<<<blocks, 64>>>(x, h0, W_ih, W_hh, b_ih, b_hh,
                                     W_out, b_out, y, h_n, B, T);
}